// round 7
// baseline (speedup 1.0000x reference)
#include <cuda_runtime.h>
#include <math.h>

#define SS 64
#define S3 (SS*SS*SS)

typedef unsigned long long u64;

// Scratch (allocation-free)
__device__ float g_hidden[64 * S3];      // [64][z][y][x]
__device__ float g_w1t[16 * 27 * 64];    // [ic][k][oc]          (oc-vector form)
__device__ float g_w2t[64 * 27 * 32];    // [ic][k][oc dup x2]   (voxel-vector form)

__device__ __forceinline__ u64 pack2(float x) {
    u64 r; asm("mov.b64 %0, {%1, %1};" : "=l"(r) : "f"(x)); return r;
}
__device__ __forceinline__ u64 mkp(float a, float b) {
    u64 r; asm("mov.b64 %0, {%1, %2};" : "=l"(r) : "f"(a), "f"(b)); return r;
}
__device__ __forceinline__ void unpack2(u64 v, float& lo, float& hi) {
    asm("mov.b64 {%0, %1}, %2;" : "=f"(lo), "=f"(hi) : "l"(v));
}
__device__ __forceinline__ u64 fma2(u64 a, u64 b, u64 c) {
    u64 d; asm("fma.rn.f32x2 %0, %1, %2, %3;" : "=l"(d) : "l"(a), "l"(b), "l"(c)); return d;
}
__device__ __forceinline__ float tanh_fast(float x) {
    float y; asm("tanh.approx.f32 %0, %1;" : "=f"(y) : "f"(x)); return y;
}

// ---------------------------------------------------------------------------
// Weight transposes
// ---------------------------------------------------------------------------
__global__ void transpose_w1(const float* __restrict__ w1) {
    int idx = blockIdx.x * 256 + threadIdx.x;
    if (idx < 16 * 27 * 64) {
        int oc = idx & 63; int r = idx >> 6; int k = r % 27; int ic = r / 27;
        g_w1t[idx] = w1[(oc * 16 + ic) * 27 + k];
    }
}
// w2 [16][64][27] -> g_w2t [ic][k][oc*2 (duplicated)]
__global__ void transpose_w2(const float* __restrict__ w2) {
    int idx = blockIdx.x * 256 + threadIdx.x;
    if (idx < 64 * 27 * 32) {
        int oc = (idx >> 1) & 15; int r = idx >> 5; int k = r % 27; int ic = r / 27;
        g_w2t[idx] = w2[(oc * 64 + ic) * 27 + k];
    }
}

// ---------------------------------------------------------------------------
// Kernel A: hidden = tanh(conv3d(y, w1) + b1)      (unchanged from R5)
// Tile 8z x 4y x 8x, 64 oc. 512 threads.
// ---------------------------------------------------------------------------
#define C1_PAD 24
#define C1_SINF (16 * 10 * 6 * C1_PAD)   // 23040 floats
#define C1_SWF  (16 * 27 * 64)           // 27648 floats
__global__ __launch_bounds__(512, 1)
void conv1_kernel(const float* __restrict__ y, const float* __restrict__ b1) {
    extern __shared__ float sm[];
    float* s_w  = sm;            // [16][27][64]
    float* s_in = sm + C1_SWF;   // [16][10z][6y][24 pad] (10 real x values)

    const int tid = threadIdx.x;
    const int x0 = blockIdx.x * 8;
    const int y0 = blockIdx.y * 4;
    const int z0 = blockIdx.z * 8;

    {   // stage weights (float4 coalesced)
        const float4* src = (const float4*)g_w1t;
        float4* dst = (float4*)s_w;
        for (int i = tid; i < C1_SWF / 4; i += 512) dst[i] = src[i];
    }
    // stage input halo tile: 16ic x 10z x 6y x 10x
    for (int idx = tid; idx < 16 * 10 * 6 * 10; idx += 512) {
        int xx = idx % 10;
        int r = idx / 10;
        int yy = r % 6; r /= 6;
        int zz = r % 10; int ic = r / 10;
        float v = 0.f;
        int gx = x0 + xx - 1, gy = y0 + yy - 1, gz = z0 + zz - 1;
        if ((unsigned)gx < SS && (unsigned)gy < SS && (unsigned)gz < SS)
            v = y[((ic * SS + gz) * SS + gy) * SS + gx];
        s_in[((ic * 10 + zz) * 6 + yy) * C1_PAD + xx] = v;
    }
    __syncthreads();

    const int og = tid >> 6;
    const int r  = tid & 63;
    const int xh = r & 1;
    const int ly = (r >> 1) & 3;
    const int lz = r >> 3;

    u64 acc[4][4];   // [voxel][oc-pair]
    #pragma unroll
    for (int v = 0; v < 4; v++)
        #pragma unroll
        for (int p = 0; p < 4; p++) acc[v][p] = 0ull;

    for (int ic = 0; ic < 16; ic++) {
        const float* in_c = s_in + ic * (10 * 6 * C1_PAD) + xh * 4;
        const float* w_c  = s_w + ic * (27 * 64) + og * 8;
        #pragma unroll
        for (int kz = 0; kz < 3; kz++)
        #pragma unroll
        for (int ky = 0; ky < 3; ky++) {
            const float* rp = in_c + ((lz + kz) * 6 + (ly + ky)) * C1_PAD;
            float4 f0 = *(const float4*)rp;         // aligned, conflict-free
            float2 f1 = *(const float2*)(rp + 4);
            u64 P[6];
            P[0] = pack2(f0.x); P[1] = pack2(f0.y); P[2] = pack2(f0.z);
            P[3] = pack2(f0.w); P[4] = pack2(f1.x); P[5] = pack2(f1.y);
            #pragma unroll
            for (int kx = 0; kx < 3; kx++) {
                const ulonglong2* wp =
                    (const ulonglong2*)(w_c + ((kz * 3 + ky) * 3 + kx) * 64);
                ulonglong2 Wa = wp[0], Wb = wp[1];   // broadcast (uniform per warp)
                u64 W[4] = {Wa.x, Wa.y, Wb.x, Wb.y};
                #pragma unroll
                for (int v = 0; v < 4; v++)
                    #pragma unroll
                    for (int p = 0; p < 4; p++)
                        acc[v][p] = fma2(P[v + kx], W[p], acc[v][p]);
            }
        }
    }

    const int gz = z0 + lz, gy = y0 + ly, gx = x0 + xh * 4;
    #pragma unroll
    for (int p = 0; p < 4; p++) {
        const int oc0 = og * 8 + 2 * p;
        const float bb0 = b1[oc0], bb1 = b1[oc0 + 1];
        float4 o0, o1; float lo, hi;
        unpack2(acc[0][p], lo, hi); o0.x = tanh_fast(lo + bb0); o1.x = tanh_fast(hi + bb1);
        unpack2(acc[1][p], lo, hi); o0.y = tanh_fast(lo + bb0); o1.y = tanh_fast(hi + bb1);
        unpack2(acc[2][p], lo, hi); o0.z = tanh_fast(lo + bb0); o1.z = tanh_fast(hi + bb1);
        unpack2(acc[3][p], lo, hi); o0.w = tanh_fast(lo + bb0); o1.w = tanh_fast(hi + bb1);
        *(float4*)&g_hidden[((oc0 * SS + gz) * SS + gy) * SS + gx] = o0;
        *(float4*)&g_hidden[(((oc0 + 1) * SS + gz) * SS + gy) * SS + gx] = o1;
    }
}

// ---------------------------------------------------------------------------
// Kernel B: y += (conv3d(hidden, w2) + b2)*dt + sigma*sqrt(dt)*noise
// Tile 8z x 8y x 8x, 16 oc. 256 threads, 2 CTAs/SM (staging overlaps compute).
//   og = tid>>6 (4 oc, warp-uniform), vg = tid&63: lz=vg>>3, ly=vg&7
// Each thread: full 8-x row as 4 voxel PAIRS (f32x2) x 4 oc (dup'd weights).
// ic chunked x8 through smem (8 chunks), weights staged per chunk.
// ---------------------------------------------------------------------------
#define C2_PAD 12
#define C2_ICC 8                                  // ic per chunk
#define C2_SINF (C2_ICC * 10 * 10 * C2_PAD)       // 9600 floats
#define C2_SWF  (C2_ICC * 27 * 32)                // 6912 floats (dup'd chunk)
__global__ __launch_bounds__(256, 2)
void conv2_kernel(float* __restrict__ y, const float* __restrict__ b2,
                  const float* __restrict__ noise) {
    extern __shared__ float sm[];
    float* s_w  = sm;            // [8][27][32]  (oc duplicated)
    float* s_in = sm + C2_SWF;   // [8][10z][10y][12 pad] (10 real x values)

    const int tid = threadIdx.x;
    const int x0 = blockIdx.x * 8;
    const int y0 = blockIdx.y * 8;
    const int z0 = blockIdx.z * 8;

    const int og = tid >> 6;
    const int vg = tid & 63;
    const int lz = vg >> 3;
    const int ly = vg & 7;

    u64 acc[4][4];   // [voxel-pair][oc]
    #pragma unroll
    for (int v = 0; v < 4; v++)
        #pragma unroll
        for (int o = 0; o < 4; o++) acc[v][o] = 0ull;

    for (int chunk = 0; chunk < 8; chunk++) {
        const int icg = chunk * C2_ICC;
        __syncthreads();
        {   // stage this chunk's dup'd weights (6912 floats = 1728 float4)
            const float4* src = (const float4*)(g_w2t + icg * 27 * 32);
            float4* dst = (float4*)s_w;
            for (int i = tid; i < C2_SWF / 4; i += 256) dst[i] = src[i];
        }
        // stage input chunk: 8ic x 10z x 10y x 10x = 8000 elems
        for (int idx = tid; idx < C2_ICC * 10 * 10 * 10; idx += 256) {
            int xx = idx % 10;
            int r = idx / 10;
            int yy = r % 10; r /= 10;
            int zz = r % 10; int ic = r / 10;
            float v = 0.f;
            int gx = x0 + xx - 1, gy = y0 + yy - 1, gz = z0 + zz - 1;
            if ((unsigned)gx < SS && (unsigned)gy < SS && (unsigned)gz < SS)
                v = g_hidden[(((icg + ic) * SS + gz) * SS + gy) * SS + gx];
            s_in[((ic * 10 + zz) * 10 + yy) * C2_PAD + xx] = v;
        }
        __syncthreads();

        for (int ic = 0; ic < C2_ICC; ic++) {
            const float* in_c = s_in + ic * (10 * 10 * C2_PAD);
            const float* w_c  = s_w + ic * (27 * 32) + og * 8;
            #pragma unroll
            for (int kz = 0; kz < 3; kz++)
            #pragma unroll
            for (int ky = 0; ky < 3; ky++) {
                const float* rp = in_c + ((lz + kz) * 10 + (ly + ky)) * C2_PAD;
                float4 a = *(const float4*)rp;
                float4 b = *(const float4*)(rp + 4);
                float2 c = *(const float2*)(rp + 8);
                u64 P[9];   // sliding (x, x+1) pairs
                P[0] = mkp(a.x, a.y); P[1] = mkp(a.y, a.z); P[2] = mkp(a.z, a.w);
                P[3] = mkp(a.w, b.x); P[4] = mkp(b.x, b.y); P[5] = mkp(b.y, b.z);
                P[6] = mkp(b.z, b.w); P[7] = mkp(b.w, c.x); P[8] = mkp(c.x, c.y);
                #pragma unroll
                for (int kx = 0; kx < 3; kx++) {
                    const ulonglong2* wp =
                        (const ulonglong2*)(w_c + ((kz * 3 + ky) * 3 + kx) * 32);
                    ulonglong2 wA = wp[0], wB = wp[1];  // broadcast; dup'd oc weights
                    u64 Wd[4] = {wA.x, wA.y, wB.x, wB.y};
                    #pragma unroll
                    for (int v = 0; v < 4; v++)
                        #pragma unroll
                        for (int o = 0; o < 4; o++)
                            acc[v][o] = fma2(P[2 * v + kx], Wd[o], acc[v][o]);
                }
            }
        }
    }

    const int gz = z0 + lz, gy = y0 + ly;
    const float dt  = 0.05f;
    const float sdt = 0.1f * 0.22360680f;   // sigma * sqrt(dt)
    #pragma unroll
    for (int o = 0; o < 4; o++) {
        const int goc = og * 4 + o;
        const float bb = b2[goc];
        const int base = ((goc * SS + gz) * SS + gy) * SS + x0;
        float4 ylo = *(const float4*)&y[base];
        float4 yhi = *(const float4*)&y[base + 4];
        float4 nlo = *(const float4*)&noise[base];
        float4 nhi = *(const float4*)&noise[base + 4];
        float q0, q1;
        unpack2(acc[0][o], q0, q1);
        ylo.x += (q0 + bb) * dt + sdt * nlo.x;
        ylo.y += (q1 + bb) * dt + sdt * nlo.y;
        unpack2(acc[1][o], q0, q1);
        ylo.z += (q0 + bb) * dt + sdt * nlo.z;
        ylo.w += (q1 + bb) * dt + sdt * nlo.w;
        unpack2(acc[2][o], q0, q1);
        yhi.x += (q0 + bb) * dt + sdt * nhi.x;
        yhi.y += (q1 + bb) * dt + sdt * nhi.y;
        unpack2(acc[3][o], q0, q1);
        yhi.z += (q0 + bb) * dt + sdt * nhi.z;
        yhi.w += (q1 + bb) * dt + sdt * nhi.w;
        *(float4*)&y[base] = ylo;
        *(float4*)&y[base + 4] = yhi;
    }
}

// ---------------------------------------------------------------------------
// Launch: y(d_out) <- x; 20x { conv1 -> conv2(update) }. Graph-capturable.
// ---------------------------------------------------------------------------
extern "C" void kernel_launch(void* const* d_in, const int* in_sizes, int n_in,
                              void* d_out, int out_size) {
    const float* x     = (const float*)d_in[0];
    // d_in[1] = integration_time (ts = [0,1], N_STEPS = 20 fixed)
    const float* w1    = (const float*)d_in[2];
    const float* b1    = (const float*)d_in[3];
    const float* w2    = (const float*)d_in[4];
    const float* b2    = (const float*)d_in[5];
    const float* noise = (const float*)d_in[6];
    float* y = (float*)d_out;

    const size_t smA = (size_t)(C1_SWF + C1_SINF) * sizeof(float);  // 202.75 KB
    const size_t smB = (size_t)(C2_SWF + C2_SINF) * sizeof(float);  // 64.5 KB
    cudaFuncSetAttribute(conv1_kernel, cudaFuncAttributeMaxDynamicSharedMemorySize, (int)smA);
    cudaFuncSetAttribute(conv2_kernel, cudaFuncAttributeMaxDynamicSharedMemorySize, (int)smB);

    cudaMemcpyAsync(y, x, (size_t)16 * S3 * sizeof(float), cudaMemcpyDeviceToDevice);
    transpose_w1<<<108, 256>>>(w1);
    transpose_w2<<<216, 256>>>(w2);

    dim3 gA(8, 16, 8);   // x/8, y/4, z/8   = 1024 CTAs
    dim3 gB(8, 8, 8);    // x/8, y/8, z/8   = 512 CTAs
    for (int step = 0; step < 20; step++) {
        conv1_kernel<<<gA, 512, smA>>>(y, b1);
        conv2_kernel<<<gB, 256, smB>>>(y, b2, noise + (size_t)step * 16 * S3);
    }
}

// round 9
// speedup vs baseline: 1.2387x; 1.2387x over previous
#include <cuda_runtime.h>
#include <math.h>

#define SS 64
#define S3 (SS*SS*SS)

typedef unsigned long long u64;

// Scratch (allocation-free)
__device__ float g_hidden[64 * S3];      // [64][z][y][x]
__device__ float g_w1t[16 * 27 * 64];    // [ic][k][oc]   (oc-vector form)
__device__ float g_w2t[64 * 27 * 16];    // [ic][k][oc]   (oc-vector form)

__device__ __forceinline__ u64 pack2(float x) {
    u64 r; asm("mov.b64 %0, {%1, %1};" : "=l"(r) : "f"(x)); return r;
}
__device__ __forceinline__ void unpack2(u64 v, float& lo, float& hi) {
    asm("mov.b64 {%0, %1}, %2;" : "=f"(lo), "=f"(hi) : "l"(v));
}
__device__ __forceinline__ u64 fma2(u64 a, u64 b, u64 c) {
    u64 d; asm("fma.rn.f32x2 %0, %1, %2, %3;" : "=l"(d) : "l"(a), "l"(b), "l"(c)); return d;
}
__device__ __forceinline__ float tanh_fast(float x) {
    float y; asm("tanh.approx.f32 %0, %1;" : "=f"(y) : "f"(x)); return y;
}

// ---------------------------------------------------------------------------
// Weight transposes
// ---------------------------------------------------------------------------
__global__ void transpose_w1(const float* __restrict__ w1) {
    int idx = blockIdx.x * 256 + threadIdx.x;
    if (idx < 16 * 27 * 64) {
        int oc = idx & 63; int r = idx >> 6; int k = r % 27; int ic = r / 27;
        g_w1t[idx] = w1[(oc * 16 + ic) * 27 + k];
    }
}
// w2 [16][64][27] -> g_w2t [ic][k][oc]
__global__ void transpose_w2(const float* __restrict__ w2) {
    int idx = blockIdx.x * 256 + threadIdx.x;
    if (idx < 64 * 27 * 16) {
        int oc = idx & 15; int r = idx >> 4; int k = r % 27; int ic = r / 27;
        g_w2t[idx] = w2[(oc * 64 + ic) * 27 + k];
    }
}

// ---------------------------------------------------------------------------
// Kernel A: hidden = tanh(conv3d(y, w1) + b1)      (unchanged — issue-saturated)
// Tile 8z x 4y x 8x, 64 oc. 512 threads.
// ---------------------------------------------------------------------------
#define C1_PAD 24
#define C1_SINF (16 * 10 * 6 * C1_PAD)   // 23040 floats
#define C1_SWF  (16 * 27 * 64)           // 27648 floats
__global__ __launch_bounds__(512, 1)
void conv1_kernel(const float* __restrict__ y, const float* __restrict__ b1) {
    extern __shared__ float sm[];
    float* s_w  = sm;            // [16][27][64]
    float* s_in = sm + C1_SWF;   // [16][10z][6y][24 pad] (10 real x values)

    const int tid = threadIdx.x;
    const int x0 = blockIdx.x * 8;
    const int y0 = blockIdx.y * 4;
    const int z0 = blockIdx.z * 8;

    {   // stage weights (float4 coalesced)
        const float4* src = (const float4*)g_w1t;
        float4* dst = (float4*)s_w;
        for (int i = tid; i < C1_SWF / 4; i += 512) dst[i] = src[i];
    }
    // stage input halo tile: 16ic x 10z x 6y x 10x
    for (int idx = tid; idx < 16 * 10 * 6 * 10; idx += 512) {
        int xx = idx % 10;
        int r = idx / 10;
        int yy = r % 6; r /= 6;
        int zz = r % 10; int ic = r / 10;
        float v = 0.f;
        int gx = x0 + xx - 1, gy = y0 + yy - 1, gz = z0 + zz - 1;
        if ((unsigned)gx < SS && (unsigned)gy < SS && (unsigned)gz < SS)
            v = y[((ic * SS + gz) * SS + gy) * SS + gx];
        s_in[((ic * 10 + zz) * 6 + yy) * C1_PAD + xx] = v;
    }
    __syncthreads();

    const int og = tid >> 6;
    const int r  = tid & 63;
    const int xh = r & 1;
    const int ly = (r >> 1) & 3;
    const int lz = r >> 3;

    u64 acc[4][4];   // [voxel][oc-pair]
    #pragma unroll
    for (int v = 0; v < 4; v++)
        #pragma unroll
        for (int p = 0; p < 4; p++) acc[v][p] = 0ull;

    for (int ic = 0; ic < 16; ic++) {
        const float* in_c = s_in + ic * (10 * 6 * C1_PAD) + xh * 4;
        const float* w_c  = s_w + ic * (27 * 64) + og * 8;
        #pragma unroll
        for (int kz = 0; kz < 3; kz++)
        #pragma unroll
        for (int ky = 0; ky < 3; ky++) {
            const float* rp = in_c + ((lz + kz) * 6 + (ly + ky)) * C1_PAD;
            float4 f0 = *(const float4*)rp;         // aligned, conflict-free
            float2 f1 = *(const float2*)(rp + 4);
            u64 P[6];
            P[0] = pack2(f0.x); P[1] = pack2(f0.y); P[2] = pack2(f0.z);
            P[3] = pack2(f0.w); P[4] = pack2(f1.x); P[5] = pack2(f1.y);
            #pragma unroll
            for (int kx = 0; kx < 3; kx++) {
                const ulonglong2* wp =
                    (const ulonglong2*)(w_c + ((kz * 3 + ky) * 3 + kx) * 64);
                ulonglong2 Wa = wp[0], Wb = wp[1];   // broadcast (uniform per warp)
                u64 W[4] = {Wa.x, Wa.y, Wb.x, Wb.y};
                #pragma unroll
                for (int v = 0; v < 4; v++)
                    #pragma unroll
                    for (int p = 0; p < 4; p++)
                        acc[v][p] = fma2(P[v + kx], W[p], acc[v][p]);
            }
        }
    }

    const int gz = z0 + lz, gy = y0 + ly, gx = x0 + xh * 4;
    #pragma unroll
    for (int p = 0; p < 4; p++) {
        const int oc0 = og * 8 + 2 * p;
        const float bb0 = b1[oc0], bb1 = b1[oc0 + 1];
        float4 o0, o1; float lo, hi;
        unpack2(acc[0][p], lo, hi); o0.x = tanh_fast(lo + bb0); o1.x = tanh_fast(hi + bb1);
        unpack2(acc[1][p], lo, hi); o0.y = tanh_fast(lo + bb0); o1.y = tanh_fast(hi + bb1);
        unpack2(acc[2][p], lo, hi); o0.z = tanh_fast(lo + bb0); o1.z = tanh_fast(hi + bb1);
        unpack2(acc[3][p], lo, hi); o0.w = tanh_fast(lo + bb0); o1.w = tanh_fast(hi + bb1);
        *(float4*)&g_hidden[((oc0 * SS + gz) * SS + gy) * SS + gx] = o0;
        *(float4*)&g_hidden[(((oc0 + 1) * SS + gz) * SS + gy) * SS + gx] = o1;
    }
}

// ---------------------------------------------------------------------------
// Kernel B (restructured, conv1-style oc-vector):
//   y += (conv3d(hidden, w2) + b2)*dt + sigma*sqrt(dt)*noise
// Tile 8z x 16y x 8x = 1024 vox. 256 threads, 2 CTAs/SM.
// Each thread: 4 x-consecutive voxels (xh half) x ALL 16 oc (8 oc-pairs).
// Lane map (within warp): xh=lane&1, ly=(lane>>1)&15 -> 32 distinct; lz uniform.
// ic chunked x4 through smem (16 chunks).
// ---------------------------------------------------------------------------
#define C2_PAD 24
#define C2_ICC 4
#define C2_SINF (C2_ICC * 10 * 18 * C2_PAD)   // 17280 floats
#define C2_SWF  (C2_ICC * 27 * 16)            // 1728 floats
__global__ __launch_bounds__(256, 2)
void conv2_kernel(float* __restrict__ y, const float* __restrict__ b2,
                  const float* __restrict__ noise) {
    extern __shared__ float sm[];
    float* s_w  = sm;            // [4][27][16]
    float* s_in = sm + C2_SWF;   // [4][10z][18y][24 pad] (10 real x values)

    const int tid = threadIdx.x;
    const int x0 = blockIdx.x * 8;
    const int y0 = blockIdx.y * 16;
    const int z0 = blockIdx.z * 8;

    const int vg = tid & 63;
    const int xh = vg & 1;
    const int ly = (vg >> 1) & 15;
    const int lz = (tid >> 6) * 2 + (vg >> 5);

    u64 acc[4][8];   // [voxel][oc-pair]
    #pragma unroll
    for (int v = 0; v < 4; v++)
        #pragma unroll
        for (int p = 0; p < 8; p++) acc[v][p] = 0ull;

    for (int chunk = 0; chunk < 16; chunk++) {
        const int icg = chunk * C2_ICC;
        __syncthreads();
        {   // stage this chunk's weights: 1728 floats = 432 float4
            const float4* src = (const float4*)(g_w2t + icg * 27 * 16);
            float4* dst = (float4*)s_w;
            for (int i = tid; i < C2_SWF / 4; i += 256) dst[i] = src[i];
        }
        // stage input chunk: 4ic x 10z x 18y x 10x = 7200 elems
        for (int idx = tid; idx < C2_ICC * 10 * 18 * 10; idx += 256) {
            int xx = idx % 10;
            int r = idx / 10;
            int yy = r % 18; r /= 18;
            int zz = r % 10; int ic = r / 10;
            float v = 0.f;
            int gx = x0 + xx - 1, gy = y0 + yy - 1, gz = z0 + zz - 1;
            if ((unsigned)gx < SS && (unsigned)gy < SS && (unsigned)gz < SS)
                v = g_hidden[(((icg + ic) * SS + gz) * SS + gy) * SS + gx];
            s_in[((ic * 10 + zz) * 18 + yy) * C2_PAD + xx] = v;
        }
        __syncthreads();

        #pragma unroll
        for (int ic = 0; ic < C2_ICC; ic++) {
            const float* in_c = s_in + ic * (10 * 18 * C2_PAD) + xh * 4;
            const float* w_c  = s_w + ic * (27 * 16);
            #pragma unroll
            for (int kz = 0; kz < 3; kz++)
            #pragma unroll
            for (int ky = 0; ky < 3; ky++) {
                const float* rp = in_c + ((lz + kz) * 18 + (ly + ky)) * C2_PAD;
                float4 f0 = *(const float4*)rp;        // conflict-free (pad 24)
                float4 f1 = *(const float4*)(rp + 4);  // conflict-free
                u64 P[7];
                P[0] = pack2(f0.x); P[1] = pack2(f0.y); P[2] = pack2(f0.z);
                P[3] = pack2(f0.w); P[4] = pack2(f1.x); P[5] = pack2(f1.y);
                P[6] = pack2(f1.z);
                #pragma unroll
                for (int kx = 0; kx < 3; kx++) {
                    const ulonglong2* wp =
                        (const ulonglong2*)(w_c + ((kz * 3 + ky) * 3 + kx) * 16);
                    ulonglong2 wA = wp[0], wB = wp[1];  // broadcast (uniform per warp)
                    u64 W[4] = {wA.x, wA.y, wB.x, wB.y};
                    #pragma unroll
                    for (int v = 0; v < 4; v++)
                        #pragma unroll
                        for (int p = 0; p < 4; p++)
                            acc[v][p] = fma2(P[v + kx], W[p], acc[v][p]);
                    const ulonglong2* wq = wp + 2;
                    ulonglong2 wC = wq[0], wD = wq[1];
                    u64 W2[4] = {wC.x, wC.y, wD.x, wD.y};
                    #pragma unroll
                    for (int v = 0; v < 4; v++)
                        #pragma unroll
                        for (int p = 0; p < 4; p++)
                            acc[v][4 + p] = fma2(P[v + kx], W2[p], acc[v][4 + p]);
                }
            }
        }
    }

    const int gz = z0 + lz, gy = y0 + ly, gx = x0 + xh * 4;
    const float dt  = 0.05f;
    const float sdt = 0.1f * 0.22360680f;   // sigma * sqrt(dt)
    #pragma unroll
    for (int p = 0; p < 8; p++) {
        const int oc0 = 2 * p;
        const float bb0 = b2[oc0], bb1 = b2[oc0 + 1];
        const int base0 = ((oc0 * SS + gz) * SS + gy) * SS + gx;
        const int base1 = (((oc0 + 1) * SS + gz) * SS + gy) * SS + gx;
        float4 y0v = *(const float4*)&y[base0];
        float4 y1v = *(const float4*)&y[base1];
        float4 n0v = *(const float4*)&noise[base0];
        float4 n1v = *(const float4*)&noise[base1];
        float lo, hi;
        unpack2(acc[0][p], lo, hi);
        y0v.x += (lo + bb0) * dt + sdt * n0v.x; y1v.x += (hi + bb1) * dt + sdt * n1v.x;
        unpack2(acc[1][p], lo, hi);
        y0v.y += (lo + bb0) * dt + sdt * n0v.y; y1v.y += (hi + bb1) * dt + sdt * n1v.y;
        unpack2(acc[2][p], lo, hi);
        y0v.z += (lo + bb0) * dt + sdt * n0v.z; y1v.z += (hi + bb1) * dt + sdt * n1v.z;
        unpack2(acc[3][p], lo, hi);
        y0v.w += (lo + bb0) * dt + sdt * n0v.w; y1v.w += (hi + bb1) * dt + sdt * n1v.w;
        *(float4*)&y[base0] = y0v;
        *(float4*)&y[base1] = y1v;
    }
}

// ---------------------------------------------------------------------------
// Launch: y(d_out) <- x; 20x { conv1 -> conv2(update) }. Graph-capturable.
// ---------------------------------------------------------------------------
extern "C" void kernel_launch(void* const* d_in, const int* in_sizes, int n_in,
                              void* d_out, int out_size) {
    const float* x     = (const float*)d_in[0];
    // d_in[1] = integration_time (ts = [0,1], N_STEPS = 20 fixed)
    const float* w1    = (const float*)d_in[2];
    const float* b1    = (const float*)d_in[3];
    const float* w2    = (const float*)d_in[4];
    const float* b2    = (const float*)d_in[5];
    const float* noise = (const float*)d_in[6];
    float* y = (float*)d_out;

    const size_t smA = (size_t)(C1_SWF + C1_SINF) * sizeof(float);  // 202.75 KB
    const size_t smB = (size_t)(C2_SWF + C2_SINF) * sizeof(float);  // 76 KB
    cudaFuncSetAttribute(conv1_kernel, cudaFuncAttributeMaxDynamicSharedMemorySize, (int)smA);
    cudaFuncSetAttribute(conv2_kernel, cudaFuncAttributeMaxDynamicSharedMemorySize, (int)smB);

    cudaMemcpyAsync(y, x, (size_t)16 * S3 * sizeof(float), cudaMemcpyDeviceToDevice);
    transpose_w1<<<108, 256>>>(w1);
    transpose_w2<<<108, 256>>>(w2);

    dim3 gA(8, 16, 8);   // x/8, y/4, z/8    = 1024 CTAs
    dim3 gB(8, 4, 8);    // x/8, y/16, z/8   = 256 CTAs
    for (int step = 0; step < 20; step++) {
        conv1_kernel<<<gA, 512, smA>>>(y, b1);
        conv2_kernel<<<gB, 256, smB>>>(y, b2, noise + (size_t)step * 16 * S3);
    }
}